// round 6
// baseline (speedup 1.0000x reference)
#include <cuda_runtime.h>
#include <math.h>

namespace {

using u64 = unsigned long long;

constexpr int B      = 4096;
constexpr int NHID   = 512;
constexpr int BR     = 32;
constexpr int NG2    = 1024;
constexpr int WSLICE = NHID * BR;
constexpr int MAXIT  = 4096;

// ---- persistent scratch ----
__device__ int   g_perm[B];
__device__ int2  g_items[MAXIT];     // {start | count<<16, node}  (L1 then L2)
__device__ int   g_nitems;
__device__ float g_q0[B];
__device__ float g_q1[B];
__device__ float g_q2[B];

// ---- f32x2 helpers (PTX-only packed FMA) ----
__device__ __forceinline__ u64 fma2(u64 a, u64 b, u64 c) {
    u64 d; asm("fma.rn.f32x2 %0, %1, %2, %3;" : "=l"(d) : "l"(a), "l"(b), "l"(c));
    return d;
}
__device__ __forceinline__ u64 add2(u64 a, u64 b) {
    u64 d; asm("add.rn.f32x2 %0, %1, %2;" : "=l"(d) : "l"(a), "l"(b));
    return d;
}
__device__ __forceinline__ u64 dup2(float x) {
    u64 d; asm("mov.b64 %0, {%1, %1};" : "=l"(d) : "r"(__float_as_uint(x)));
    return d;
}
__device__ __forceinline__ float lo32(u64 a) { return __uint_as_float((unsigned)a); }
__device__ __forceinline__ float hi32(u64 a) { return __uint_as_float((unsigned)(a >> 32)); }

__device__ __forceinline__ int warp_incl_scan(int v) {
    int lane = threadIdx.x & 31;
    #pragma unroll
    for (int o = 1; o < 32; o <<= 1) {
        int n = __shfl_up_sync(0xffffffffu, v, o);
        if (lane >= o) v += n;
    }
    return v;
}

// ---- shared GEMV+softmax body: one warp, 8 samples, one node ----
// USE_PERM: idx via g_perm (kernel B) vs natural order (kernel A / level 0)
template <bool USE_PERM>
__device__ __forceinline__ void gemv_item(
    const float* __restrict__ inputs,
    const int*   __restrict__ labels,
    const float* __restrict__ W,
    int start, int count, int node, int lane)
{
    const int cg = lane & 7;      // 4-column group
    const int hs = lane >> 3;     // h-stripe within 16-chunk

    int shift;
    float* qdst;
    if (node == 0)      { shift = 10; qdst = g_q0; }
    else if (node < 33) { shift = 5;  qdst = g_q1; }
    else                { shift = 0;  qdst = g_q2; }

    int idx[8];
    u64 steps = 0;    // 5 bits per sample
    const float* xp[8];
    #pragma unroll
    for (int s = 0; s < 8; s++) {
        int pos = start + ((s < count) ? s : (count - 1));
        int i = USE_PERM ? g_perm[pos] : pos;
        idx[s] = i;
        steps |= (u64)((labels[i] >> shift) & 31) << (5 * s);
        xp[s]  = inputs + (size_t)i * NHID;
    }

    const float* __restrict__ Wn = W + (size_t)node * WSLICE + cg * 4;

    u64 acc0[8], acc1[8];       // (c0,c1),(c2,c3) packed per sample
    #pragma unroll
    for (int s = 0; s < 8; s++) { acc0[s] = 0ull; acc1[s] = 0ull; }

    for (int hb = 0; hb < NHID; hb += 16) {
        const int h0 = hb + hs * 4;
        ulonglong2 wv[4];
        #pragma unroll
        for (int j = 0; j < 4; j++)
            wv[j] = *(const ulonglong2*)&Wn[(h0 + j) * BR];
        float4 xv[8];
        #pragma unroll
        for (int s = 0; s < 8; s++)
            xv[s] = *(const float4*)&xp[s][h0];
        #pragma unroll
        for (int j = 0; j < 4; j++) {
            #pragma unroll
            for (int s = 0; s < 8; s++) {
                const u64 xd = dup2((&xv[s].x)[j]);
                acc0[s] = fma2(wv[j].x, xd, acc0[s]);
                acc1[s] = fma2(wv[j].y, xd, acc1[s]);
            }
        }
    }

    // reduce over the 4 h-stripes (lanes cg, cg+8, cg+16, cg+24)
    #pragma unroll
    for (int o = 8; o <= 16; o <<= 1)
        #pragma unroll
        for (int s = 0; s < 8; s++) {
            acc0[s] = add2(acc0[s], __shfl_xor_sync(0xffffffffu, acc0[s], o));
            acc1[s] = add2(acc1[s], __shfl_xor_sync(0xffffffffu, acc1[s], o));
        }

    // per-sample softmax across the 8 column-group lanes
    #pragma unroll
    for (int s = 0; s < 8; s++) {
        const int st = (int)(steps >> (5 * s)) & 31;
        const float a0 = lo32(acc0[s]), a1 = hi32(acc0[s]);
        const float a2 = lo32(acc1[s]), a3 = hi32(acc1[s]);
        float mx = fmaxf(fmaxf(a0, a1), fmaxf(a2, a3));
        #pragma unroll
        for (int o = 1; o < 8; o <<= 1)
            mx = fmaxf(mx, __shfl_xor_sync(0xffffffffu, mx, o));
        float e = __expf(a0 - mx) + __expf(a1 - mx) + __expf(a2 - mx) + __expf(a3 - mx);
        #pragma unroll
        for (int o = 1; o < 8; o <<= 1)
            e += __shfl_xor_sync(0xffffffffu, e, o);
        const float lse = mx + __logf(e);
        const int r = st & 3;
        float v = (r == 0) ? a0 : (r == 1) ? a1 : (r == 2) ? a2 : a3;
        float sel = (cg == (st >> 2)) ? v : -INFINITY;
        #pragma unroll
        for (int o = 1; o < 8; o <<= 1)
            sel = fmaxf(sel, __shfl_xor_sync(0xffffffffu, sel, o));
        if (s < count && lane == s) qdst[idx[s]] = sel - lse;
    }
}

// ---- 256-thread sort: histogram by leaf group, scan, scatter, L1+L2 items ----
__device__ void sort256(const int* __restrict__ labels)
{
    __shared__ int scnt[NG2];
    __shared__ int soff[NG2 + 1];
    __shared__ int srun[NG2];
    __shared__ int sA[8], sB[8];
    __shared__ int s_tot1;

    const int tid  = threadIdx.x;
    const int lane = tid & 31;
    const int w    = tid >> 5;

    for (int k = tid; k < NG2; k += 256) { scnt[k] = 0; srun[k] = 0; }
    __syncthreads();

    int4 lab4[4];
    #pragma unroll
    for (int k = 0; k < 4; k++) {
        lab4[k] = ((const int4*)labels)[tid + 256 * k];
        atomicAdd(&scnt[lab4[k].x >> 5], 1);
        atomicAdd(&scnt[lab4[k].y >> 5], 1);
        atomicAdd(&scnt[lab4[k].z >> 5], 1);
        atomicAdd(&scnt[lab4[k].w >> 5], 1);
    }
    __syncthreads();

    // scan 1: exclusive offsets (4 bins per thread)
    const int base = tid * 4;
    const int c0 = scnt[base], c1 = scnt[base + 1], c2 = scnt[base + 2], c3 = scnt[base + 3];
    const int csum = c0 + c1 + c2 + c3;
    {
        int inc = warp_incl_scan(csum);
        if (lane == 31) sA[w] = inc;
        __syncthreads();
        if (w == 0) {
            int t = (lane < 8) ? sA[lane] : 0;
            int ti = warp_incl_scan(t);
            if (lane < 8) sA[lane] = ti - t;
        }
        __syncthreads();
        int off = inc - csum + sA[w];
        soff[base]     = off;
        soff[base + 1] = off + c0;
        soff[base + 2] = off + c0 + c1;
        soff[base + 3] = off + c0 + c1 + c2;
        if (tid == 255) soff[NG2] = off + csum;
    }
    __syncthreads();

    // scan 2: level-2 item offsets (batch of 8 per leaf group)
    const int n0 = (c0 + 7) >> 3, n1 = (c1 + 7) >> 3, n2 = (c2 + 7) >> 3, n3 = (c3 + 7) >> 3;
    const int nsum = n0 + n1 + n2 + n3;
    int ioff2, tot2;
    {
        int inc2 = warp_incl_scan(nsum);
        if (lane == 31) sB[w] = inc2;
        __syncthreads();
        if (w == 0) {
            int t = (lane < 8) ? sB[lane] : 0;
            int ti = warp_incl_scan(t);
            if (lane < 8) sB[lane] = ti - t;
            if (lane == 7) sB[0] = ti;   // total (reused after sync)
        }
        __syncthreads();
        tot2  = sB[0];
        // careful: sB[0] was overwritten; recompute exclusive base for w==0 as 0
        ioff2 = inc2 - nsum + ((w == 0) ? 0 : sB[w]);
    }

    // scatter into g_perm
    #pragma unroll
    for (int k = 0; k < 4; k++) {
        int i = (tid + 256 * k) * 4;
        int ga = lab4[k].x >> 5, gb = lab4[k].y >> 5, gc = lab4[k].z >> 5, gd = lab4[k].w >> 5;
        g_perm[soff[ga] + atomicAdd(&srun[ga], 1)] = i;
        g_perm[soff[gb] + atomicAdd(&srun[gb], 1)] = i + 1;
        g_perm[soff[gc] + atomicAdd(&srun[gc], 1)] = i + 2;
        g_perm[soff[gd] + atomicAdd(&srun[gd], 1)] = i + 3;
    }

    // L1 items (32 groups of 32 leaf groups), batch 8
    if (w == 0) {
        int st1 = soff[lane * 32];
        int cg1 = soff[(lane + 1) * 32] - st1;
        int nit1 = (cg1 + 7) >> 3;
        int i1 = warp_incl_scan(nit1);
        int it1off = i1 - nit1;
        int tot1 = __shfl_sync(0xffffffffu, i1, 31);
        if (lane == 0) s_tot1 = tot1;
        for (int k = 0; k < nit1; k++) {
            int cc = min(8, cg1 - 8 * k);
            g_items[it1off + k] = make_int2((st1 + 8 * k) | (cc << 16), 1 + lane);
        }
    }
    __syncthreads();
    const int tot1 = s_tot1;

    // L2 items (4 bins per thread), appended after L1 items
    {
        int o = tot1 + ioff2;
        int cs[4] = {c0, c1, c2, c3};
        int ns[4] = {n0, n1, n2, n3};
        #pragma unroll
        for (int bidx = 0; bidx < 4; bidx++) {
            int st = soff[base + bidx];
            for (int k = 0; k < ns[bidx]; k++) {
                int cc = min(8, cs[bidx] - 8 * k);
                g_items[o++] = make_int2((st + 8 * k) | (cc << 16), 33 + base + bidx);
            }
        }
    }

    if (tid == 0) g_nitems = tot1 + tot2;
}

// ================= kernel A: level-0 compute (blocks 0..146) + sort (block 147) ==========
__global__ __launch_bounds__(256)
void hs_A(const float* __restrict__ inputs,
          const int*   __restrict__ labels,
          const float* __restrict__ W)
{
    if (blockIdx.x == 147) { sort256(labels); return; }

    const int w    = threadIdx.x >> 5;
    const int lane = threadIdx.x & 31;
    const int item = w * 147 + blockIdx.x;   // spread across SMs
    if (item >= 512) return;
    gemv_item<false>(inputs, labels, W, item * 8, 8, 0, lane);
}

// ================= kernel B: L1 + L2 items ==========
__global__ __launch_bounds__(256)
void hs_B(const float* __restrict__ inputs,
          const int*   __restrict__ labels,
          const float* __restrict__ W)
{
    const int lane = threadIdx.x & 31;
    const int gw   = (blockIdx.x << 3) + (threadIdx.x >> 5);
    const int nw   = gridDim.x << 3;
    const int nit  = g_nitems;

    for (int it = gw; it < nit; it += nw) {
        const int2 item  = g_items[it];
        gemv_item<true>(inputs, labels, W,
                        item.x & 0xffff, item.x >> 16, item.y, lane);
    }
}

__global__ void hs_combine(float* __restrict__ out)
{
    int i = blockIdx.x * blockDim.x + threadIdx.x;   // 16 x 256
    out[i] = __expf(g_q0[i] + g_q1[i] + g_q2[i]);
}

} // namespace

extern "C" void kernel_launch(void* const* d_in, const int* in_sizes, int n_in,
                              void* d_out, int out_size)
{
    const float* inputs = (const float*)d_in[0];
    const int*   labels = (const int*)d_in[1];
    const float* W      = (const float*)d_in[2];
    float*       out    = (float*)d_out;

    hs_A      <<<148, 256>>>(inputs, labels, W);
    hs_B      <<<200, 256>>>(inputs, labels, W);
    hs_combine<<<16, 256>>>(out);
}

// round 8
// speedup vs baseline: 1.2831x; 1.2831x over previous
#include <cuda_runtime.h>
#include <math.h>

namespace {

using u64 = unsigned long long;

constexpr int B      = 4096;
constexpr int NHID   = 512;
constexpr int BR     = 32;
constexpr int NG2    = 1024;
constexpr int WSLICE = NHID * BR;
constexpr int MAXIT  = 4096;
constexpr int NIT0   = 1024;         // level-0 items (batch 4, static)

// ---- persistent scratch ----
__device__ int   g_cnt[NG2];         // zeroed by hs_combine each run
__device__ int   g_run[NG2];         // zeroed by hs_combine each run
__device__ int   g_off[NG2 + 1];
__device__ int   g_perm[B];
__device__ int2  g_items[MAXIT];     // {start | count<<16, node}  (L1 then L2)
__device__ int   g_nitems;           // L1+L2 item count
__device__ float g_q0[B];
__device__ float g_q1[B];
__device__ float g_q2[B];

// ---- f32x2 helpers ----
__device__ __forceinline__ u64 fma2(u64 a, u64 b, u64 c) {
    u64 d; asm("fma.rn.f32x2 %0, %1, %2, %3;" : "=l"(d) : "l"(a), "l"(b), "l"(c));
    return d;
}
__device__ __forceinline__ u64 pack2(float lo, float hi) {
    u64 d; asm("mov.b64 %0, {%1, %2};" : "=l"(d) : "f"(lo), "f"(hi));
    return d;
}
__device__ __forceinline__ float lo32(u64 a) { return __uint_as_float((unsigned)a); }
__device__ __forceinline__ float hi32(u64 a) { return __uint_as_float((unsigned)(a >> 32)); }

__device__ __forceinline__ int warp_incl_scan(int v) {
    int lane = threadIdx.x & 31;
    #pragma unroll
    for (int o = 1; o < 32; o <<= 1) {
        int n = __shfl_up_sync(0xffffffffu, v, o);
        if (lane >= o) v += n;
    }
    return v;
}

// ================= K1: histogram (grid-wide) =================
__global__ void hs_hist(const int* __restrict__ labels)
{
    int i = blockIdx.x * blockDim.x + threadIdx.x;   // 16 x 256
    atomicAdd(&g_cnt[labels[i] >> 5], 1);
}

// ================= K2: scan + item build (1 block, 1024 threads) ===========
__global__ __launch_bounds__(1024)
void hs_scan()
{
    __shared__ int sA[33];
    __shared__ int sB[33];
    __shared__ int soff[NG2 + 1];
    __shared__ int s_tot1;

    const int tid  = threadIdx.x;
    const int lane = tid & 31;
    const int w    = tid >> 5;

    const int c = g_cnt[tid];

    // scan 1: exclusive group offsets
    {
        int inc = warp_incl_scan(c);
        if (lane == 31) sA[w] = inc;
        __syncthreads();
        if (w == 0) { int t = sA[lane]; int ti = warp_incl_scan(t); sA[lane] = ti - t; }
        __syncthreads();
        int off = inc - c + sA[w];
        soff[tid] = off;
        g_off[tid] = off;
        if (tid == NG2 - 1) { soff[NG2] = off + c; g_off[NG2] = off + c; }
    }
    __syncthreads();
    const int off = soff[tid];

    // scan 2: level-2 item offsets (batch 4 per leaf group)
    const int nit2 = (c + 3) >> 2;
    int ioff2, tot2;
    {
        int inc2 = warp_incl_scan(nit2);
        if (lane == 31) sB[w] = inc2;
        __syncthreads();
        if (w == 0) {
            int t = sB[lane]; int ti = warp_incl_scan(t);
            sB[lane] = ti - t;
            if (lane == 31) sB[32] = ti;
        }
        __syncthreads();
        ioff2 = inc2 - nit2 + sB[w];
        tot2  = sB[32];
    }

    // L1 items (32 groups of 32 leaf groups), batch 4
    if (tid < 32) {
        int st1 = soff[tid * 32];
        int c1  = soff[(tid + 1) * 32] - st1;
        int nit1 = (c1 + 3) >> 2;
        int i1 = warp_incl_scan(nit1);
        int it1off = i1 - nit1;
        int tot1 = __shfl_sync(0xffffffffu, i1, 31);
        if (tid == 0) s_tot1 = tot1;
        for (int k = 0; k < nit1; k++) {
            int cc = min(4, c1 - 4 * k);
            g_items[it1off + k] = make_int2((st1 + 4 * k) | (cc << 16), 1 + tid);
        }
    }
    __syncthreads();
    const int tot1 = s_tot1;

    // L2 items, batch 4
    for (int k = 0; k < nit2; k++) {
        int cc = min(4, c - 4 * k);
        g_items[tot1 + ioff2 + k] = make_int2((off + 4 * k) | (cc << 16), 33 + tid);
    }

    if (tid == 0) g_nitems = tot1 + tot2;
}

// ================= K3: scatter (grid-wide) =================
__global__ void hs_scatter(const int* __restrict__ labels)
{
    int i = blockIdx.x * blockDim.x + threadIdx.x;   // 16 x 256
    int g = labels[i] >> 5;
    int pos = g_off[g] + atomicAdd(&g_run[g], 1);
    g_perm[pos] = i;
}

// ================= main: one warp per item, batch 4, h-pair packed =========
__global__ __launch_bounds__(128)
void hs_main(const float* __restrict__ inputs,
             const int*   __restrict__ labels,
             const float* __restrict__ W)
{
    const int lane = threadIdx.x & 31;
    const int cg   = lane & 7;      // 4-column group
    const int hs   = lane >> 3;     // h-stripe within 16-chunk
    const int gw   = (blockIdx.x << 2) + (threadIdx.x >> 5);
    const int nw   = gridDim.x << 2;
    const int nit  = NIT0 + g_nitems;

    for (int it = gw; it < nit; it += nw) {
        int start, count, node;
        if (it < NIT0) { start = it * 4; count = 4; node = 0; }
        else {
            const int2 t = g_items[it - NIT0];
            start = t.x & 0xffff; count = t.x >> 16; node = t.y;
        }
        const bool use_perm = (it >= NIT0);

        int shift;
        float* qdst;
        if (node == 0)      { shift = 10; qdst = g_q0; }
        else if (node < 33) { shift = 5;  qdst = g_q1; }
        else                { shift = 0;  qdst = g_q2; }

        int idx[4];
        unsigned steps = 0;   // 5 bits per sample
        const float* xp[4];
        #pragma unroll
        for (int s = 0; s < 4; s++) {
            int pos = start + ((s < count) ? s : (count - 1));
            int i = use_perm ? g_perm[pos] : pos;
            idx[s] = i;
            steps |= (unsigned)((labels[i] >> shift) & 31) << (5 * s);
            xp[s]  = inputs + (size_t)i * NHID;
        }

        const float* __restrict__ Wn = W + (size_t)node * WSLICE + cg * 4;

        u64 acc[4][4];   // [sample][col], packed (even_h, odd_h) partials
        #pragma unroll
        for (int s = 0; s < 4; s++)
            #pragma unroll
            for (int cc = 0; cc < 4; cc++) acc[s][cc] = 0ull;

        for (int hb = 0; hb < NHID; hb += 16) {
            const int h0 = hb + hs * 4;
            const float4 w0 = *(const float4*)&Wn[(h0 + 0) * BR];
            const float4 w1 = *(const float4*)&Wn[(h0 + 1) * BR];
            const float4 w2 = *(const float4*)&Wn[(h0 + 2) * BR];
            const float4 w3 = *(const float4*)&Wn[(h0 + 3) * BR];
            ulonglong2 xv[4];
            #pragma unroll
            for (int s = 0; s < 4; s++)
                xv[s] = *(const ulonglong2*)&xp[s][h0];

            u64 p01[4], p23[4];
            p01[0] = pack2(w0.x, w1.x); p01[1] = pack2(w0.y, w1.y);
            p01[2] = pack2(w0.z, w1.z); p01[3] = pack2(w0.w, w1.w);
            p23[0] = pack2(w2.x, w3.x); p23[1] = pack2(w2.y, w3.y);
            p23[2] = pack2(w2.z, w3.z); p23[3] = pack2(w2.w, w3.w);

            #pragma unroll
            for (int cc = 0; cc < 4; cc++)
                #pragma unroll
                for (int s = 0; s < 4; s++) {
                    acc[s][cc] = fma2(p01[cc], xv[s].x, acc[s][cc]);
                    acc[s][cc] = fma2(p23[cc], xv[s].y, acc[s][cc]);
                }
        }

        // collapse packed halves, then reduce over 4 h-stripes
        float a[4][4];
        #pragma unroll
        for (int s = 0; s < 4; s++)
            #pragma unroll
            for (int cc = 0; cc < 4; cc++)
                a[s][cc] = lo32(acc[s][cc]) + hi32(acc[s][cc]);
        #pragma unroll
        for (int o = 8; o <= 16; o <<= 1)
            #pragma unroll
            for (int s = 0; s < 4; s++)
                #pragma unroll
                for (int cc = 0; cc < 4; cc++)
                    a[s][cc] += __shfl_xor_sync(0xffffffffu, a[s][cc], o);

        // per-sample softmax across the 8 column-group lanes
        #pragma unroll
        for (int s = 0; s < 4; s++) {
            const int st = (int)(steps >> (5 * s)) & 31;
            float mx = fmaxf(fmaxf(a[s][0], a[s][1]), fmaxf(a[s][2], a[s][3]));
            #pragma unroll
            for (int o = 1; o < 8; o <<= 1)
                mx = fmaxf(mx, __shfl_xor_sync(0xffffffffu, mx, o));
            float e = __expf(a[s][0] - mx) + __expf(a[s][1] - mx)
                    + __expf(a[s][2] - mx) + __expf(a[s][3] - mx);
            #pragma unroll
            for (int o = 1; o < 8; o <<= 1)
                e += __shfl_xor_sync(0xffffffffu, e, o);
            const float lse = mx + __logf(e);
            const int r = st & 3;
            float v = (r == 0) ? a[s][0] : (r == 1) ? a[s][1]
                    : (r == 2) ? a[s][2] : a[s][3];
            float sel = (cg == (st >> 2)) ? v : -INFINITY;
            #pragma unroll
            for (int o = 1; o < 8; o <<= 1)
                sel = fmaxf(sel, __shfl_xor_sync(0xffffffffu, sel, o));
            if (s < count && lane == s) qdst[idx[s]] = sel - lse;
        }
    }
}

// ================= combine + reset counters for next replay =================
__global__ void hs_combine(float* __restrict__ out)
{
    int i = blockIdx.x * blockDim.x + threadIdx.x;   // 16 x 256
    out[i] = __expf(g_q0[i] + g_q1[i] + g_q2[i]);
    if (i < NG2)               g_cnt[i] = 0;
    else if (i < 2 * NG2)      g_run[i - NG2] = 0;
}

} // namespace

extern "C" void kernel_launch(void* const* d_in, const int* in_sizes, int n_in,
                              void* d_out, int out_size)
{
    const float* inputs = (const float*)d_in[0];
    const int*   labels = (const int*)d_in[1];
    const float* W      = (const float*)d_in[2];
    float*       out    = (float*)d_out;

    hs_hist   <<<16, 256>>>(labels);
    hs_scan   <<<1, 1024>>>();
    hs_scatter<<<16, 256>>>(labels);
    hs_main   <<<592, 128>>>(inputs, labels, W);
    hs_combine<<<16, 256>>>(out);
}

// round 9
// speedup vs baseline: 1.6795x; 1.3090x over previous
#include <cuda_runtime.h>
#include <math.h>

namespace {

using u64 = unsigned long long;

constexpr int B      = 4096;
constexpr int NHID   = 512;
constexpr int BR     = 32;
constexpr int NG2    = 1024;
constexpr int WSLICE = NHID * BR;
constexpr int MAXIT  = 2048;
constexpr int NIT0   = 512;          // level-0 items (batch 8, static)

// ---- persistent scratch ----
__device__ int   g_cnt[NG2];         // zeroed by hs_combine each run
__device__ int   g_run[NG2];         // zeroed by hs_combine each run
__device__ int   g_off[NG2 + 1];
__device__ int   g_perm[B];
__device__ int2  g_items[MAXIT];     // {start | count<<16, node}  (L1 then L2)
__device__ int   g_nitems;           // L1+L2 item count
__device__ float g_q0[B];
__device__ float g_q1[B];
__device__ float g_q2[B];

// ---- f32x2 helpers (PTX-only packed FMA) ----
__device__ __forceinline__ u64 fma2(u64 a, u64 b, u64 c) {
    u64 d; asm("fma.rn.f32x2 %0, %1, %2, %3;" : "=l"(d) : "l"(a), "l"(b), "l"(c));
    return d;
}
__device__ __forceinline__ u64 add2(u64 a, u64 b) {
    u64 d; asm("add.rn.f32x2 %0, %1, %2;" : "=l"(d) : "l"(a), "l"(b));
    return d;
}
__device__ __forceinline__ u64 dup2(float x) {
    u64 d; asm("mov.b64 %0, {%1, %1};" : "=l"(d) : "r"(__float_as_uint(x)));
    return d;
}
__device__ __forceinline__ float lo32(u64 a) { return __uint_as_float((unsigned)a); }
__device__ __forceinline__ float hi32(u64 a) { return __uint_as_float((unsigned)(a >> 32)); }

__device__ __forceinline__ int warp_incl_scan(int v) {
    int lane = threadIdx.x & 31;
    #pragma unroll
    for (int o = 1; o < 32; o <<= 1) {
        int n = __shfl_up_sync(0xffffffffu, v, o);
        if (lane >= o) v += n;
    }
    return v;
}

// ================= K1: histogram (grid-wide) =================
__global__ void hs_hist(const int* __restrict__ labels)
{
    int i = blockIdx.x * blockDim.x + threadIdx.x;   // 16 x 256
    atomicAdd(&g_cnt[labels[i] >> 5], 1);
}

// ================= K2: scan + item build (1 block, 1024 threads) ===========
__global__ __launch_bounds__(1024)
void hs_scan()
{
    __shared__ int sA[33];
    __shared__ int sB[33];
    __shared__ int soff[NG2 + 1];
    __shared__ int s_tot1;

    const int tid  = threadIdx.x;
    const int lane = tid & 31;
    const int w    = tid >> 5;

    const int c = g_cnt[tid];

    // scan 1: exclusive group offsets
    {
        int inc = warp_incl_scan(c);
        if (lane == 31) sA[w] = inc;
        __syncthreads();
        if (w == 0) { int t = sA[lane]; int ti = warp_incl_scan(t); sA[lane] = ti - t; }
        __syncthreads();
        int off = inc - c + sA[w];
        soff[tid] = off;
        g_off[tid] = off;
        if (tid == NG2 - 1) { soff[NG2] = off + c; g_off[NG2] = off + c; }
    }
    __syncthreads();
    const int off = soff[tid];

    // scan 2: level-2 item offsets (batch 8 per leaf group)
    const int nit2 = (c + 7) >> 3;
    int ioff2, tot2;
    {
        int inc2 = warp_incl_scan(nit2);
        if (lane == 31) sB[w] = inc2;
        __syncthreads();
        if (w == 0) {
            int t = sB[lane]; int ti = warp_incl_scan(t);
            sB[lane] = ti - t;
            if (lane == 31) sB[32] = ti;
        }
        __syncthreads();
        ioff2 = inc2 - nit2 + sB[w];
        tot2  = sB[32];
    }

    // L1 items (32 groups of 32 leaf groups), batch 8
    if (tid < 32) {
        int st1 = soff[tid * 32];
        int c1  = soff[(tid + 1) * 32] - st1;
        int nit1 = (c1 + 7) >> 3;
        int i1 = warp_incl_scan(nit1);
        int it1off = i1 - nit1;
        int tot1 = __shfl_sync(0xffffffffu, i1, 31);
        if (tid == 0) s_tot1 = tot1;
        for (int k = 0; k < nit1; k++) {
            int cc = min(8, c1 - 8 * k);
            g_items[it1off + k] = make_int2((st1 + 8 * k) | (cc << 16), 1 + tid);
        }
    }
    __syncthreads();
    const int tot1 = s_tot1;

    // L2 items, batch 8
    for (int k = 0; k < nit2; k++) {
        int cc = min(8, c - 8 * k);
        g_items[tot1 + ioff2 + k] = make_int2((off + 8 * k) | (cc << 16), 33 + tid);
    }

    if (tid == 0) g_nitems = tot1 + tot2;
}

// ================= K3: scatter (grid-wide) =================
__global__ void hs_scatter(const int* __restrict__ labels)
{
    int i = blockIdx.x * blockDim.x + threadIdx.x;   // 16 x 256
    int g = labels[i] >> 5;
    int pos = g_off[g] + atomicAdd(&g_run[g], 1);
    g_perm[pos] = i;
}

// ================= main: one warp per item, batch 8 (R5 core) =================
__global__ __launch_bounds__(256)
void hs_main(const float* __restrict__ inputs,
             const int*   __restrict__ labels,
             const float* __restrict__ W)
{
    const int lane = threadIdx.x & 31;
    const int cg   = lane & 7;      // 4-column group
    const int hs   = lane >> 3;     // h-stripe within 16-chunk
    const int gw   = (blockIdx.x << 3) + (threadIdx.x >> 5);
    const int nw   = gridDim.x << 3;
    const int nit  = NIT0 + g_nitems;

    for (int it = gw; it < nit; it += nw) {
        int start, count, node;
        bool use_perm;
        if (it < NIT0) { start = it * 8; count = 8; node = 0; use_perm = false; }
        else {
            const int2 t = g_items[it - NIT0];
            start = t.x & 0xffff; count = t.x >> 16; node = t.y;
            use_perm = true;
        }

        int shift;
        float* qdst;
        if (node == 0)      { shift = 10; qdst = g_q0; }
        else if (node < 33) { shift = 5;  qdst = g_q1; }
        else                { shift = 0;  qdst = g_q2; }

        int idx[8];
        u64 steps = 0;    // 5 bits per sample
        const float* xp[8];
        #pragma unroll
        for (int s = 0; s < 8; s++) {
            int pos = start + ((s < count) ? s : (count - 1));
            int i = use_perm ? g_perm[pos] : pos;
            idx[s] = i;
            steps |= (u64)((labels[i] >> shift) & 31) << (5 * s);
            xp[s]  = inputs + (size_t)i * NHID;
        }

        const float* __restrict__ Wn = W + (size_t)node * WSLICE + cg * 4;

        u64 acc0[8], acc1[8];       // (c0,c1),(c2,c3) packed per sample
        #pragma unroll
        for (int s = 0; s < 8; s++) { acc0[s] = 0ull; acc1[s] = 0ull; }

        for (int hb = 0; hb < NHID; hb += 16) {
            const int h0 = hb + hs * 4;
            ulonglong2 wv[4];
            #pragma unroll
            for (int j = 0; j < 4; j++)
                wv[j] = *(const ulonglong2*)&Wn[(h0 + j) * BR];
            float4 xv[8];
            #pragma unroll
            for (int s = 0; s < 8; s++)
                xv[s] = *(const float4*)&xp[s][h0];
            #pragma unroll
            for (int j = 0; j < 4; j++) {
                #pragma unroll
                for (int s = 0; s < 8; s++) {
                    const u64 xd = dup2((&xv[s].x)[j]);
                    acc0[s] = fma2(wv[j].x, xd, acc0[s]);
                    acc1[s] = fma2(wv[j].y, xd, acc1[s]);
                }
            }
        }

        // reduce over the 4 h-stripes (lanes cg, cg+8, cg+16, cg+24)
        #pragma unroll
        for (int o = 8; o <= 16; o <<= 1)
            #pragma unroll
            for (int s = 0; s < 8; s++) {
                acc0[s] = add2(acc0[s], __shfl_xor_sync(0xffffffffu, acc0[s], o));
                acc1[s] = add2(acc1[s], __shfl_xor_sync(0xffffffffu, acc1[s], o));
            }

        // per-sample softmax across the 8 column-group lanes
        #pragma unroll
        for (int s = 0; s < 8; s++) {
            const int st = (int)(steps >> (5 * s)) & 31;   // warp-uniform
            const float a0 = lo32(acc0[s]), a1 = hi32(acc0[s]);
            const float a2 = lo32(acc1[s]), a3 = hi32(acc1[s]);
            float mx = fmaxf(fmaxf(a0, a1), fmaxf(a2, a3));
            #pragma unroll
            for (int o = 1; o < 8; o <<= 1)
                mx = fmaxf(mx, __shfl_xor_sync(0xffffffffu, mx, o));
            float e = __expf(a0 - mx) + __expf(a1 - mx) + __expf(a2 - mx) + __expf(a3 - mx);
            #pragma unroll
            for (int o = 1; o < 8; o <<= 1)
                e += __shfl_xor_sync(0xffffffffu, e, o);
            const float lse = mx + __logf(e);
            // selected logit: lane (st>>2) within each 8-lane group holds it;
            // st is warp-uniform, so a single indexed shuffle broadcasts it.
            const int r = st & 3;
            const float v = (r == 0) ? a0 : (r == 1) ? a1 : (r == 2) ? a2 : a3;
            const float sel = __shfl_sync(0xffffffffu, v, (lane & 24) | (st >> 2));
            if (s < count && lane == s) qdst[idx[s]] = sel - lse;
        }
    }
}

// ================= combine + reset counters for next replay =================
__global__ void hs_combine(float* __restrict__ out)
{
    int i = blockIdx.x * blockDim.x + threadIdx.x;   // 16 x 256
    out[i] = __expf(g_q0[i] + g_q1[i] + g_q2[i]);
    if (i < NG2)          g_cnt[i] = 0;
    else if (i < 2 * NG2) g_run[i - NG2] = 0;
}

} // namespace

extern "C" void kernel_launch(void* const* d_in, const int* in_sizes, int n_in,
                              void* d_out, int out_size)
{
    const float* inputs = (const float*)d_in[0];
    const int*   labels = (const int*)d_in[1];
    const float* W      = (const float*)d_in[2];
    float*       out    = (float*)d_out;

    hs_hist   <<<16, 256>>>(labels);
    hs_scan   <<<1, 1024>>>();
    hs_scatter<<<16, 256>>>(labels);
    hs_main   <<<296, 256>>>(inputs, labels, W);
    hs_combine<<<16, 256>>>(out);
}